// round 8
// baseline (speedup 1.0000x reference)
#include <cuda_runtime.h>
#include <cuda_bf16.h>

#define FULL_MASK 0xFFFFFFFFu

// 4 lanes per row, 8 rows per warp, 128-thread blocks (small blocks reduce
// retirement-granularity occupancy holes from decide-length variance).
// Decide: per 16-column block, ONE int4 nidx load per lane (cols 0..15,
// self col masked), then two gather rounds of 2 parallel gathers per lane:
//   round A -> components {x,y}  (decides ~7/8 of rows)
//   round B -> components {z,w}  (cumulative 15/16)
// This keeps gather count ~9/row while cutting the serialized latency chain
// from ~3 x (nidx-DRAM + gather-L2) to (nidx-DRAM + 1-2 x gather-L2).
__global__ void __launch_bounds__(128)
dgb_kernel(const float4* __restrict__ dist4,
           const int*    __restrict__ nidx,
           const float*  __restrict__ score,
           float4* __restrict__ dist_out4,
           float4* __restrict__ nidx_out4,
           long long V)
{
    long long warp_id = ((long long)blockIdx.x * blockDim.x + threadIdx.x) >> 5;
    int lane = threadIdx.x & 31;
    int g = lane >> 2;                 // row group within warp: 0..7
    int l = lane & 3;                  // lane within group: 0..3
    unsigned grpmask = 0xFu << (g << 2);

    long long row = warp_id * 8 + g;
    bool valid = row < V;
    long long srow = valid ? row : 0;

    float sv = valid ? __ldg(score + row) : 3.0f;   // >1 => never beaten
    const int4* nq = (const int4*)(nidx + srow * 64);

    bool cond = false;                 // true => some neighbour beats sv
    #pragma unroll 1
    for (int b = 0; b < 4; ++b) {
        int4 q = __ldg(nq + b * 4 + l);          // cols b*16+4l .. +3
        int c0 = (b << 4) + (l << 2);            // column of q.x

        // round A: components x,y (parallel predicated gathers)
        {
            float vx = __ldg(score + max(q.x, 0));
            float vy = __ldg(score + max(q.y, 0));
            bool beat = ((c0 != 0) & (q.x >= 0) & (vx > sv)) |
                        ((q.y >= 0) & (vy > sv));
            if (__any_sync(grpmask, beat)) { cond = true; break; }
        }
        // round B: components z,w
        {
            float vz = __ldg(score + max(q.z, 0));
            float vw = __ldg(score + max(q.w, 0));
            bool beat = ((q.z >= 0) & (vz > sv)) |
                        ((q.w >= 0) & (vw > sv));
            if (__any_sync(grpmask, beat)) { cond = true; break; }
        }
    }

    // Publish cond bits for all 8 rows of this warp (bit at lane g*4).
    unsigned bal = __ballot_sync(FULL_MASK, cond);

    // ---- write phase: contiguous streaming over the warp's 8 rows ----
    long long warp_row0 = warp_id * 8;
    long long gbase = warp_row0 * 16;  // float4 index of region start
    const int4* nidx4 = (const int4*)nidx;

    #pragma unroll
    for (int t = 0; t < 4; ++t) {
        int vec = t * 32 + lane;       // 0..127 within warp region
        int row_local = vec >> 4;      // 0..7
        int within = vec & 15;         // float4 within row
        long long rr = warp_row0 + row_local;
        if (rr >= V) continue;
        long long idx = gbase + vec;

        bool c = (bal >> (row_local << 2)) & 1u;

        float4 dv, nv;
        if (c) {
            dv = make_float4(0.f, 0.f, 0.f, 0.f);
            nv = make_float4(-1.f, -1.f, -1.f, -1.f);
            if (within == 0) nv.x = (float)rr;
        } else {
            dv = __ldg(dist4 + idx);
            int4 niv = __ldg(nidx4 + idx);
            nv = make_float4((float)niv.x, (float)niv.y,
                             (float)niv.z, (float)niv.w);
        }
        dist_out4[idx] = dv;
        nidx_out4[idx] = nv;
    }
}

extern "C" void kernel_launch(void* const* d_in, const int* in_sizes, int n_in,
                              void* d_out, int out_size)
{
    const float* dist  = (const float*)d_in[0];   // [V, 64] f32
    const int*   nidx  = (const int*)d_in[1];     // [V, 64] i32
    const float* score = (const float*)d_in[2];   // [V, 1]  f32

    long long V = in_sizes[2];                    // score element count == V

    float* out      = (float*)d_out;
    float* dist_out = out;                        // first V*64 floats
    float* nidx_out = out + V * 64;               // second V*64 (ints as f32)

    // 4 lanes per row -> V*4 threads
    long long total_threads = V * 4;
    int threads = 128;
    long long blocks = (total_threads + threads - 1) / threads;

    dgb_kernel<<<(unsigned int)blocks, threads>>>(
        (const float4*)dist, nidx, score,
        (float4*)dist_out, (float4*)nidx_out, V);
}

// round 9
// speedup vs baseline: 1.1140x; 1.1140x over previous
#include <cuda_runtime.h>
#include <cuda_bf16.h>

#define FULL_MASK 0xFFFFFFFFu

// R3 decide scheme (best known: 107us) with 128-thread blocks (R8 evidence:
// smaller blocks cut the block-retirement occupancy leak, 74.6% -> 82.8%).
// 4 lanes per row, 8 rows per warp. Early-exit scan over columns 1..63
// (column 0 = self, never gathered) in chunks of 4, per-group exit.
// Write phase streams the warp's 8 contiguous rows coalesced (512B/instr).
__global__ void __launch_bounds__(128)
dgb_kernel(const float4* __restrict__ dist4,
           const int*    __restrict__ nidx,
           const float*  __restrict__ score,
           float4* __restrict__ dist_out4,
           float4* __restrict__ nidx_out4,
           long long V)
{
    long long warp_id = ((long long)blockIdx.x * blockDim.x + threadIdx.x) >> 5;
    int lane = threadIdx.x & 31;
    int g = lane >> 2;                 // row group within warp: 0..7
    int l = lane & 3;                  // lane within group: 0..3
    unsigned grpmask = 0xFu << (g << 2);

    long long row = warp_id * 8 + g;
    bool valid = row < V;
    long long srow = valid ? row : 0;

    float sv = valid ? __ldg(score + row) : 3.0f;   // >1 => never beaten
    const int* nrow = nidx + srow * 64;

    // ---- early-exit decide: chunks of 4 over columns 1..63 ----
    bool cond = false;                 // true => some neighbour beats sv
    #pragma unroll 1
    for (int j = 0; j < 16; ++j) {
        int col = (j << 2) + 1 + l;    // 1..64 (64 guarded off)
        bool beat = false;
        if (col < 64) {
            int ni = __ldg(nrow + col);
            if (ni >= 0)
                beat = __ldg(score + ni) > sv;   // strict: matches diff < 0
        }
        if (__any_sync(grpmask, beat)) { cond = true; break; }
    }

    // Publish cond bits for all 8 rows of this warp (bit at lane g*4).
    unsigned bal = __ballot_sync(FULL_MASK, cond);

    // ---- write phase: contiguous streaming over the warp's 8 rows ----
    long long warp_row0 = warp_id * 8;
    long long gbase = warp_row0 * 16;  // float4 index of region start
    const int4* nidx4 = (const int4*)nidx;

    #pragma unroll
    for (int t = 0; t < 4; ++t) {
        int vec = t * 32 + lane;       // 0..127 within warp region
        int row_local = vec >> 4;      // 0..7
        int within = vec & 15;         // float4 within row
        long long rr = warp_row0 + row_local;
        if (rr >= V) continue;
        long long idx = gbase + vec;

        bool c = (bal >> (row_local << 2)) & 1u;

        float4 dv, nv;
        if (c) {
            dv = make_float4(0.f, 0.f, 0.f, 0.f);
            nv = make_float4(-1.f, -1.f, -1.f, -1.f);
            if (within == 0) nv.x = (float)rr;
        } else {
            dv = __ldg(dist4 + idx);
            int4 niv = __ldg(nidx4 + idx);
            nv = make_float4((float)niv.x, (float)niv.y,
                             (float)niv.z, (float)niv.w);
        }
        dist_out4[idx] = dv;
        nidx_out4[idx] = nv;
    }
}

extern "C" void kernel_launch(void* const* d_in, const int* in_sizes, int n_in,
                              void* d_out, int out_size)
{
    const float* dist  = (const float*)d_in[0];   // [V, 64] f32
    const int*   nidx  = (const int*)d_in[1];     // [V, 64] i32
    const float* score = (const float*)d_in[2];   // [V, 1]  f32

    long long V = in_sizes[2];                    // score element count == V

    float* out      = (float*)d_out;
    float* dist_out = out;                        // first V*64 floats
    float* nidx_out = out + V * 64;               // second V*64 (ints as f32)

    // 4 lanes per row -> V*4 threads
    long long total_threads = V * 4;
    int threads = 128;
    long long blocks = (total_threads + threads - 1) / threads;

    dgb_kernel<<<(unsigned int)blocks, threads>>>(
        (const float4*)dist, nidx, score,
        (float4*)dist_out, (float4*)nidx_out, V);
}